// round 15
// baseline (speedup 1.0000x reference)
#include <cuda_runtime.h>

#define Bq 32
#define Tq 512
#define Hq 512
#define FFq 2048

typedef unsigned long long u64;
typedef unsigned int u32;

// ---------------- static device scratch ---------------------------------------
__device__ float g_Uf[Bq*Tq*Hq];
__device__ float g_Ub[Bq*Tq*Hq];
__device__ float g_Z [Bq*Tq*2*Hq];
__device__ float g_A [Bq*Tq*FFq];
__device__ float g_h [2*2*Bq*Hq];       // [dir][pingpong][b*H+j]
__device__ float g_S [Bq*2*Hq];
__device__ float g_As[Bq*FFq];
__device__ unsigned g_bar2[512];         // 16 group counters, 128B apart
__device__ int   g_off[Bq];
__device__ int   g_nv;
__device__ int   g_idx[Bq*Tq];
__device__ float g_c2p[16][2*Hq];
__device__ float g_c2[2*Hq];

__device__ __forceinline__ u64 pk2(float lo, float hi) {
    u64 r; asm("mov.b64 %0, {%1, %2};" : "=l"(r) : "f"(lo), "f"(hi)); return r;
}
__device__ __forceinline__ void fma2(u64& d, u64 a, u64 b) {
    asm("fma.rn.f32x2 %0, %1, %2, %0;" : "+l"(d) : "l"(a), "l"(b));
}
__device__ __forceinline__ float2 upk(u64 v) {
    float2 f; asm("mov.b64 {%0, %1}, %2;" : "=f"(f.x), "=f"(f.y) : "l"(v)); return f;
}
__device__ __forceinline__ u32 f2tf32(float f) {
    u32 r; asm("cvt.rna.tf32.f32 %0, %1;" : "=r"(r) : "f"(f)); return r;
}

// ---------------- init ----------------------------------------------------------
__global__ void init_kernel() {
    int idx = blockIdx.x * blockDim.x + threadIdx.x;
    if (idx < (2*2*Bq*Hq)/4)
        ((float4*)g_h)[idx] = make_float4(0.f, 0.f, 0.f, 0.f);
    if (idx < 512) g_bar2[idx] = 0u;
}

// ---------------- compaction helpers -------------------------------------------
__global__ void scan_kernel(const int* __restrict__ length) {
    if (threadIdx.x == 0 && blockIdx.x == 0) {
        int acc = 0;
        for (int b = 0; b < Bq; ++b) { g_off[b] = acc; acc += length[b]; }
        g_nv = acc;
    }
}

__global__ void idx_kernel(const int* __restrict__ length) {
    int i = blockIdx.x * blockDim.x + threadIdx.x;
    if (i < Bq * Tq) {
        int b = i >> 9, t = i & 511;
        if (t < length[b]) g_idx[g_off[b] + t] = i;
    }
}

__global__ void c2_part_kernel(const float* __restrict__ b1,
                               const float* __restrict__ W2) {
    int n = blockIdx.x * blockDim.x + threadIdx.x;
    int f0 = blockIdx.y * 128;
    float s = 0.f;
    for (int f = f0; f < f0 + 128; ++f)
        s += tanhf(b1[f]) * W2[(size_t)f * 2*Hq + n];
    g_c2p[blockIdx.y][n] = s;
}

__global__ void c2_sum_kernel(const float* __restrict__ b2) {
    int n = blockIdx.x * blockDim.x + threadIdx.x;
    if (n < 2*Hq) {
        float s = 0.f;
        #pragma unroll
        for (int p = 0; p < 16; ++p) s += g_c2p[p][n];
        g_c2[n] = s + b2[n];
    }
}

__global__ void fill_kernel(const int* __restrict__ length, float* __restrict__ out) {
    int m = blockIdx.x;
    int b = m >> 9, t = m & 511;
    if (t >= length[b]) {
        float4* o = (float4*)(out + (size_t)m * 2*Hq);
        const float4* c = (const float4*)g_c2;
        for (int i = threadIdx.x; i < (2*Hq)/4; i += blockDim.x) o[i] = c[i];
    }
}

// ---------------- TF32 tensor-core GEMM (unchanged) -----------------------------
#define MMA_TF32(d, a, b0, b1)                                                  \
    asm volatile("mma.sync.aligned.m16n8k8.row.col.f32.tf32.tf32.f32 "          \
        "{%0,%1,%2,%3}, {%4,%5,%6,%7}, {%8,%9}, {%0,%1,%2,%3};"                 \
        : "+f"(d[0]), "+f"(d[1]), "+f"(d[2]), "+f"(d[3])                        \
        : "r"(a[0]), "r"(a[1]), "r"(a[2]), "r"(a[3]), "r"(b0), "r"(b1))

__global__ void __launch_bounds__(256, 2) gemm_tc(
    const float* __restrict__ A, const float* __restrict__ B,
    const float* __restrict__ bias, float* __restrict__ C,
    int M, int N, int K, int act,
    const int* __restrict__ idxA, const int* __restrict__ idxC,
    const int* __restrict__ nvp)
{
    __shared__ u32 As_t[32*132];
    __shared__ u32 Bs  [32*132];

    const int bn = blockIdx.x, bm = blockIdx.y;
    const int Meff = nvp ? *nvp : M;
    if (bm * 128 >= Meff) return;

    const int tid  = threadIdx.x;
    const int wid  = tid >> 5;
    const int lane = tid & 31;
    const int g    = lane >> 2;
    const int t4   = lane & 3;
    const int warpM = (wid & 3) * 32;
    const int warpN = (wid >> 2) * 64;

    float acc[2][8][4];
    #pragma unroll
    for (int ma = 0; ma < 2; ++ma)
        #pragma unroll
        for (int na = 0; na < 8; ++na)
            #pragma unroll
            for (int c = 0; c < 4; ++c) acc[ma][na][c] = 0.f;

    const int arow = tid >> 1;
    const int akb  = (tid & 1) * 16;
    const int brow = tid >> 3;
    const int bcg  = (tid & 7) * 16;
    const int grow = bm * 128 + arow;
    const bool aok = grow < Meff;
    const int ra = aok ? (idxA ? idxA[grow] : grow) : 0;
    const float* Ap = A + (size_t)ra * K + akb;
    const float* Bp = B + (size_t)brow * N + bn * 128 + bcg;

    float4 pa[4], pb[4];
    #pragma unroll
    for (int q = 0; q < 4; ++q) {
        pa[q] = aok ? *(const float4*)(Ap + 4*q) : make_float4(0.f,0.f,0.f,0.f);
        pb[q] = *(const float4*)(Bp + 4*q);
    }

    for (int k0 = 0; k0 < K; k0 += 32) {
        __syncthreads();
        #pragma unroll
        for (int q = 0; q < 4; ++q) {
            const float* e = (const float*)&pa[q];
            #pragma unroll
            for (int c = 0; c < 4; ++c)
                As_t[(akb + 4*q + c)*132 + arow] = f2tf32(e[c]);
            const float* f = (const float*)&pb[q];
            #pragma unroll
            for (int c = 0; c < 4; ++c)
                Bs[brow*132 + bcg + 4*q + c] = f2tf32(f[c]);
        }
        __syncthreads();

        if (k0 + 32 < K) {
            #pragma unroll
            for (int q = 0; q < 4; ++q) {
                pa[q] = aok ? *(const float4*)(Ap + k0 + 32 + 4*q)
                            : make_float4(0.f,0.f,0.f,0.f);
                pb[q] = *(const float4*)(Bp + (size_t)(k0 + 32) * N + 4*q);
            }
        }

        #pragma unroll
        for (int kk = 0; kk < 4; ++kk) {
            const int kof = kk * 8;
            u32 afr[2][4];
            const int ab = (kof + t4)*132 + warpM + g;
            #pragma unroll
            for (int ma = 0; ma < 2; ++ma) {
                afr[ma][0] = As_t[ab + ma*16];
                afr[ma][1] = As_t[ab + ma*16 + 8];
                afr[ma][2] = As_t[ab + ma*16 + 4*132];
                afr[ma][3] = As_t[ab + ma*16 + 8 + 4*132];
            }
            const int bb = (kof + t4)*132 + warpN + g;
            #pragma unroll
            for (int na = 0; na < 8; ++na) {
                u32 b0 = Bs[bb + na*8];
                u32 b1 = Bs[bb + na*8 + 4*132];
                MMA_TF32(acc[0][na], afr[0], b0, b1);
                MMA_TF32(acc[1][na], afr[1], b0, b1);
            }
        }
    }

    int rdst[2][2];
    #pragma unroll
    for (int ma = 0; ma < 2; ++ma)
        #pragma unroll
        for (int h = 0; h < 2; ++h) {
            int r = bm * 128 + warpM + ma*16 + g + h*8;
            rdst[ma][h] = (r < Meff) ? (idxC ? idxC[r] : r) : -1;
        }

    #pragma unroll
    for (int na = 0; na < 8; ++na) {
        const int col = bn * 128 + warpN + na*8 + 2*t4;
        const float2 bv = *(const float2*)&bias[col];
        #pragma unroll
        for (int ma = 0; ma < 2; ++ma) {
            float o0 = acc[ma][na][0] + bv.x;
            float o1 = acc[ma][na][1] + bv.y;
            float o2 = acc[ma][na][2] + bv.x;
            float o3 = acc[ma][na][3] + bv.y;
            if (act) { o0 = tanhf(o0); o1 = tanhf(o1); o2 = tanhf(o2); o3 = tanhf(o3); }
            if (rdst[ma][0] >= 0)
                *(float2*)&C[(size_t)rdst[ma][0] * N + col] = make_float2(o0, o1);
            if (rdst[ma][1] >= 0)
                *(float2*)&C[(size_t)rdst[ma][1] * N + col] = make_float2(o2, o3);
        }
    }
}

// ---------------- persistent bidirectional RNN, bgroup 4 / jgroup 64 ------------
// grid 128: CTA = (dir, bgroup of 4 b, jgroup of 64 j). Warp = 64-k slice,
// lane = (bi 0..1 -> 2 b rows, ji 0..15 -> j {ji, ji+16, ji+32, ji+48}).
// Same per-output arithmetic as R14. Barrier per (dir,bgroup): 8 CTAs.
#define RNN_SMEM ((64*516 + 4*512 + 8*272) * 4)

__global__ void __launch_bounds__(256, 1) rnn_kernel(
    const int* __restrict__ length,
    const float* __restrict__ Wf_h, const float* __restrict__ Wb_h)
{
    extern __shared__ float sm[];
    float*  Whs  = sm;                        // [64 j][516]
    float4* h_s4 = (float4*)(sm + 64 * 516);  // [4 b][128 float4]
    float*  red  = sm + 64 * 516 + 4 * 512;   // [warp][b*68 + j]

    const int tid  = threadIdx.x;
    const int wid  = tid >> 5;
    const int lane = tid & 31;
    const int bi   = lane >> 4;               // 0..1
    const int ji   = lane & 15;               // 0..15
    const int bx   = blockIdx.x;
    const int dir  = bx >> 6;
    const int bg   = (bx >> 3) & 7;
    const int jg   = bx & 7;
    const int b0   = bg * 4;
    const int j0   = jg * 64;
    const float* W = dir ? Wb_h : Wf_h;
    const float* U = dir ? g_Ub : g_Uf;
    float* hbase   = g_h + dir * 2 * (Bq*Hq);
    unsigned* bar  = &g_bar2[(dir * 8 + bg) * 32];

    int smax = 1;
    #pragma unroll
    for (int i = 0; i < 4; ++i) { int Lg = length[b0 + i]; if (Lg > smax) smax = Lg; }

    // load W slice: Whs[j][k] = W[k][j0+j]
    for (int i = tid; i < 64 * 512; i += 256) {
        int j = i & 63, k = i >> 6;
        Whs[j * 516 + k] = W[k * Hq + j0 + j];
    }

    const int rb = tid >> 6;                  // 0..3 (update phase b)
    const int rj = tid & 63;                  // 0..63 (update phase j)
    const int L  = length[b0 + rb];
    float hprev = 0.f;

    const int kq0 = wid * 16;
    const int bA  = bi * 2;
    __syncthreads();

    for (int s = 0; s < smax; ++s) {
        const float4* hin4 = (const float4*)(hbase + (s & 1) * (Bq*Hq));
        float* hout        = hbase + ((s + 1) & 1) * (Bq*Hq);

        // ---- prefetch U (off critical path)
        float uval = 0.f;
        int tt = 0;
        if (s < L) {
            tt = dir ? (L - 1 - s) : s;
            uval = __ldcg(&U[((size_t)((b0 + rb) * Tq + tt)) * Hq + j0 + rj]);
        }

        // ---- stage this group's 4 h rows (8KB): 2 float4/thread
        #pragma unroll
        for (int it = 0; it < 2; ++it) {
            int f = tid + it * 256;
            int b = f >> 7, c4 = f & 127;
            h_s4[b * 128 + c4] = __ldcg(hin4 + (b0 + b) * 128 + c4);
        }
        __syncthreads();

        // ---- compute partial dots (same mix as R14: 2 h bcast + 4 W LDS + 16 fma2)
        u64 acc[2][4];
        #pragma unroll
        for (int ib = 0; ib < 2; ++ib)
            #pragma unroll
            for (int jc = 0; jc < 4; ++jc) acc[ib][jc] = 0ull;

        #pragma unroll 8
        for (int it = 0; it < 16; ++it) {
            int kq = kq0 + it;
            int k  = kq * 4;
            float4 h0 = h_s4[(bA + 0) * 128 + kq];
            float4 h1 = h_s4[(bA + 1) * 128 + kq];
            ulonglong2 wA = *(const ulonglong2*)&Whs[ji * 516 + k];
            ulonglong2 wB = *(const ulonglong2*)&Whs[(ji + 16) * 516 + k];
            ulonglong2 wC = *(const ulonglong2*)&Whs[(ji + 32) * 516 + k];
            ulonglong2 wD = *(const ulonglong2*)&Whs[(ji + 48) * 516 + k];
            const ulonglong2* hv;
            hv = (const ulonglong2*)&h0;
            fma2(acc[0][0], hv->x, wA.x); fma2(acc[0][0], hv->y, wA.y);
            fma2(acc[0][1], hv->x, wB.x); fma2(acc[0][1], hv->y, wB.y);
            fma2(acc[0][2], hv->x, wC.x); fma2(acc[0][2], hv->y, wC.y);
            fma2(acc[0][3], hv->x, wD.x); fma2(acc[0][3], hv->y, wD.y);
            hv = (const ulonglong2*)&h1;
            fma2(acc[1][0], hv->x, wA.x); fma2(acc[1][0], hv->y, wA.y);
            fma2(acc[1][1], hv->x, wB.x); fma2(acc[1][1], hv->y, wB.y);
            fma2(acc[1][2], hv->x, wC.x); fma2(acc[1][2], hv->y, wC.y);
            fma2(acc[1][3], hv->x, wD.x); fma2(acc[1][3], hv->y, wD.y);
        }

        #pragma unroll
        for (int ib = 0; ib < 2; ++ib)
            #pragma unroll
            for (int jc = 0; jc < 4; ++jc) {
                float2 p = upk(acc[ib][jc]);
                red[wid * 272 + (bA + ib) * 68 + (ji + 16 * jc)] = p.x + p.y;
            }
        __syncthreads();

        float dot = 0.f;
        #pragma unroll
        for (int w = 0; w < 8; ++w) dot += red[w * 272 + rb * 68 + rj];

        float hnew;
        if (s < L) {
            hnew = tanhf(uval + dot);
            g_Z[((size_t)((b0 + rb) * Tq + tt)) * (2*Hq) + dir * Hq + j0 + rj] = hnew;
        } else {
            hnew = hprev;
        }
        hprev = hnew;
        hout[(b0 + rb) * Hq + j0 + rj] = hnew;

        // ---- group barrier (8 CTAs)
        __syncthreads();
        if (tid == 0) {
            asm volatile("red.release.gpu.global.add.u32 [%0], 1;" :: "l"(bar) : "memory");
            unsigned tgt = (unsigned)(s + 1) * 8u;
            unsigned v;
            do {
                asm volatile("ld.acquire.gpu.u32 %0, [%1];" : "=r"(v) : "l"(bar));
            } while (v < tgt);
        }
        __syncthreads();
    }

    // final states straight from registers
    g_S[(size_t)(b0 + rb) * (2*Hq) + dir * Hq + j0 + rj] = hprev;
}

// ---------------- launcher ------------------------------------------------------
extern "C" void kernel_launch(void* const* d_in, const int* in_sizes, int n_in,
                              void* d_out, int out_size) {
    const float* x      = (const float*)d_in[0];
    const int*   length = (const int*)  d_in[1];
    const float* Wf     = (const float*)d_in[2];
    const float* bf     = (const float*)d_in[3];
    const float* Wb     = (const float*)d_in[4];
    const float* bb     = (const float*)d_in[5];
    const float* W1     = (const float*)d_in[6];
    const float* b1     = (const float*)d_in[7];
    const float* W2     = (const float*)d_in[8];
    const float* b2     = (const float*)d_in[9];
    float* out = (float*)d_out;

    void *pUf, *pUb, *pZ, *pA, *pS, *pAs, *pIdx, *pNv;
    cudaGetSymbolAddress(&pUf, g_Uf);
    cudaGetSymbolAddress(&pUb, g_Ub);
    cudaGetSymbolAddress(&pZ,  g_Z);
    cudaGetSymbolAddress(&pA,  g_A);
    cudaGetSymbolAddress(&pS,  g_S);
    cudaGetSymbolAddress(&pAs, g_As);
    cudaGetSymbolAddress(&pIdx, g_idx);
    cudaGetSymbolAddress(&pNv,  g_nv);
    const int* idx = (const int*)pIdx;
    const int* nv  = (const int*)pNv;

    cudaFuncSetAttribute(rnn_kernel, cudaFuncAttributeMaxDynamicSharedMemorySize, RNN_SMEM);

    const int M = Bq * Tq;   // 16384

    init_kernel<<<64, 256>>>();
    scan_kernel<<<1, 32>>>(length);
    idx_kernel<<<(M + 255)/256, 256>>>(length);
    c2_part_kernel<<<dim3(4, 16), 256>>>(b1, W2);
    c2_sum_kernel<<<(2*Hq + 255)/256, 256>>>(b2);
    fill_kernel<<<M, 64>>>(length, out);

    gemm_tc<<<dim3(Hq/128, M/128), 256>>>(x, Wf, bf, (float*)pUf, M, Hq, Hq, 0, idx, idx, nv);
    gemm_tc<<<dim3(Hq/128, M/128), 256>>>(x, Wb, bb, (float*)pUb, M, Hq, Hq, 0, idx, idx, nv);

    rnn_kernel<<<128, 256, RNN_SMEM>>>(length, Wf + Hq*Hq, Wb + Hq*Hq);

    gemm_tc<<<dim3(FFq/128, M/128), 256>>>((const float*)pZ, W1, b1, (float*)pA, M, FFq, 2*Hq, 1, idx, (const int*)0, nv);
    gemm_tc<<<dim3((2*Hq)/128, M/128), 256>>>((const float*)pA, W2, b2, out, M, 2*Hq, FFq, 0, (const int*)0, idx, nv);

    gemm_tc<<<dim3(FFq/128, 1), 256>>>((const float*)pS, W1, b1, (float*)pAs, Bq, FFq, 2*Hq, 1, (const int*)0, (const int*)0, (const int*)0);
    gemm_tc<<<dim3((2*Hq)/128, 1), 256>>>((const float*)pAs, W2, b2, out + (size_t)M * 2 * Hq, Bq, 2*Hq, FFq, 0, (const int*)0, (const int*)0, (const int*)0);
}

// round 16
// speedup vs baseline: 1.0265x; 1.0265x over previous
#include <cuda_runtime.h>

#define Bq 32
#define Tq 512
#define Hq 512
#define FFq 2048

typedef unsigned long long u64;
typedef unsigned int u32;

// ---------------- static device scratch ---------------------------------------
__device__ float g_Uf[Bq*Tq*Hq];
__device__ float g_Ub[Bq*Tq*Hq];
__device__ float g_Z [Bq*Tq*2*Hq];
__device__ float g_A [Bq*Tq*FFq];
__device__ float g_h [2*2*Bq*Hq];       // [dir][pingpong][b*H+j]
__device__ float g_S [Bq*2*Hq];
__device__ float g_As[Bq*FFq];
__device__ int   g_off[Bq];
__device__ int   g_nv;
__device__ int   g_idx[Bq*Tq];
__device__ float g_c2p[16][2*Hq];
__device__ float g_c2[2*Hq];

__device__ __forceinline__ u64 pk2(float lo, float hi) {
    u64 r; asm("mov.b64 %0, {%1, %2};" : "=l"(r) : "f"(lo), "f"(hi)); return r;
}
__device__ __forceinline__ void fma2(u64& d, u64 a, u64 b) {
    asm("fma.rn.f32x2 %0, %1, %2, %0;" : "+l"(d) : "l"(a), "l"(b));
}
__device__ __forceinline__ float2 upk(u64 v) {
    float2 f; asm("mov.b64 {%0, %1}, %2;" : "=f"(f.x), "=f"(f.y) : "l"(v)); return f;
}
__device__ __forceinline__ u32 f2tf32(float f) {
    u32 r; asm("cvt.rna.tf32.f32 %0, %1;" : "=r"(r) : "f"(f)); return r;
}

// ---------------- init ----------------------------------------------------------
__global__ void init_kernel() {
    int idx = blockIdx.x * blockDim.x + threadIdx.x;
    if (idx < (2*2*Bq*Hq)/4)
        ((float4*)g_h)[idx] = make_float4(0.f, 0.f, 0.f, 0.f);
}

// ---------------- compaction helpers -------------------------------------------
__global__ void scan_kernel(const int* __restrict__ length) {
    if (threadIdx.x == 0 && blockIdx.x == 0) {
        int acc = 0;
        for (int b = 0; b < Bq; ++b) { g_off[b] = acc; acc += length[b]; }
        g_nv = acc;
    }
}

__global__ void idx_kernel(const int* __restrict__ length) {
    int i = blockIdx.x * blockDim.x + threadIdx.x;
    if (i < Bq * Tq) {
        int b = i >> 9, t = i & 511;
        if (t < length[b]) g_idx[g_off[b] + t] = i;
    }
}

__global__ void c2_part_kernel(const float* __restrict__ b1,
                               const float* __restrict__ W2) {
    int n = blockIdx.x * blockDim.x + threadIdx.x;
    int f0 = blockIdx.y * 128;
    float s = 0.f;
    for (int f = f0; f < f0 + 128; ++f)
        s += tanhf(b1[f]) * W2[(size_t)f * 2*Hq + n];
    g_c2p[blockIdx.y][n] = s;
}

__global__ void c2_sum_kernel(const float* __restrict__ b2) {
    int n = blockIdx.x * blockDim.x + threadIdx.x;
    if (n < 2*Hq) {
        float s = 0.f;
        #pragma unroll
        for (int p = 0; p < 16; ++p) s += g_c2p[p][n];
        g_c2[n] = s + b2[n];
    }
}

__global__ void fill_kernel(const int* __restrict__ length, float* __restrict__ out) {
    int m = blockIdx.x;
    int b = m >> 9, t = m & 511;
    if (t >= length[b]) {
        float4* o = (float4*)(out + (size_t)m * 2*Hq);
        const float4* c = (const float4*)g_c2;
        for (int i = threadIdx.x; i < (2*Hq)/4; i += blockDim.x) o[i] = c[i];
    }
}

// ---------------- TF32 tensor-core GEMM (unchanged) -----------------------------
#define MMA_TF32(d, a, b0, b1)                                                  \
    asm volatile("mma.sync.aligned.m16n8k8.row.col.f32.tf32.tf32.f32 "          \
        "{%0,%1,%2,%3}, {%4,%5,%6,%7}, {%8,%9}, {%0,%1,%2,%3};"                 \
        : "+f"(d[0]), "+f"(d[1]), "+f"(d[2]), "+f"(d[3])                        \
        : "r"(a[0]), "r"(a[1]), "r"(a[2]), "r"(a[3]), "r"(b0), "r"(b1))

__global__ void __launch_bounds__(256, 2) gemm_tc(
    const float* __restrict__ A, const float* __restrict__ B,
    const float* __restrict__ bias, float* __restrict__ C,
    int M, int N, int K, int act,
    const int* __restrict__ idxA, const int* __restrict__ idxC,
    const int* __restrict__ nvp)
{
    __shared__ u32 As_t[32*132];
    __shared__ u32 Bs  [32*132];

    const int bn = blockIdx.x, bm = blockIdx.y;
    const int Meff = nvp ? *nvp : M;
    if (bm * 128 >= Meff) return;

    const int tid  = threadIdx.x;
    const int wid  = tid >> 5;
    const int lane = tid & 31;
    const int g    = lane >> 2;
    const int t4   = lane & 3;
    const int warpM = (wid & 3) * 32;
    const int warpN = (wid >> 2) * 64;

    float acc[2][8][4];
    #pragma unroll
    for (int ma = 0; ma < 2; ++ma)
        #pragma unroll
        for (int na = 0; na < 8; ++na)
            #pragma unroll
            for (int c = 0; c < 4; ++c) acc[ma][na][c] = 0.f;

    const int arow = tid >> 1;
    const int akb  = (tid & 1) * 16;
    const int brow = tid >> 3;
    const int bcg  = (tid & 7) * 16;
    const int grow = bm * 128 + arow;
    const bool aok = grow < Meff;
    const int ra = aok ? (idxA ? idxA[grow] : grow) : 0;
    const float* Ap = A + (size_t)ra * K + akb;
    const float* Bp = B + (size_t)brow * N + bn * 128 + bcg;

    float4 pa[4], pb[4];
    #pragma unroll
    for (int q = 0; q < 4; ++q) {
        pa[q] = aok ? *(const float4*)(Ap + 4*q) : make_float4(0.f,0.f,0.f,0.f);
        pb[q] = *(const float4*)(Bp + 4*q);
    }

    for (int k0 = 0; k0 < K; k0 += 32) {
        __syncthreads();
        #pragma unroll
        for (int q = 0; q < 4; ++q) {
            const float* e = (const float*)&pa[q];
            #pragma unroll
            for (int c = 0; c < 4; ++c)
                As_t[(akb + 4*q + c)*132 + arow] = f2tf32(e[c]);
            const float* f = (const float*)&pb[q];
            #pragma unroll
            for (int c = 0; c < 4; ++c)
                Bs[brow*132 + bcg + 4*q + c] = f2tf32(f[c]);
        }
        __syncthreads();

        if (k0 + 32 < K) {
            #pragma unroll
            for (int q = 0; q < 4; ++q) {
                pa[q] = aok ? *(const float4*)(Ap + k0 + 32 + 4*q)
                            : make_float4(0.f,0.f,0.f,0.f);
                pb[q] = *(const float4*)(Bp + (size_t)(k0 + 32) * N + 4*q);
            }
        }

        #pragma unroll
        for (int kk = 0; kk < 4; ++kk) {
            const int kof = kk * 8;
            u32 afr[2][4];
            const int ab = (kof + t4)*132 + warpM + g;
            #pragma unroll
            for (int ma = 0; ma < 2; ++ma) {
                afr[ma][0] = As_t[ab + ma*16];
                afr[ma][1] = As_t[ab + ma*16 + 8];
                afr[ma][2] = As_t[ab + ma*16 + 4*132];
                afr[ma][3] = As_t[ab + ma*16 + 8 + 4*132];
            }
            const int bb = (kof + t4)*132 + warpN + g;
            #pragma unroll
            for (int na = 0; na < 8; ++na) {
                u32 b0 = Bs[bb + na*8];
                u32 b1 = Bs[bb + na*8 + 4*132];
                MMA_TF32(acc[0][na], afr[0], b0, b1);
                MMA_TF32(acc[1][na], afr[1], b0, b1);
            }
        }
    }

    int rdst[2][2];
    #pragma unroll
    for (int ma = 0; ma < 2; ++ma)
        #pragma unroll
        for (int h = 0; h < 2; ++h) {
            int r = bm * 128 + warpM + ma*16 + g + h*8;
            rdst[ma][h] = (r < Meff) ? (idxC ? idxC[r] : r) : -1;
        }

    #pragma unroll
    for (int na = 0; na < 8; ++na) {
        const int col = bn * 128 + warpN + na*8 + 2*t4;
        const float2 bv = *(const float2*)&bias[col];
        #pragma unroll
        for (int ma = 0; ma < 2; ++ma) {
            float o0 = acc[ma][na][0] + bv.x;
            float o1 = acc[ma][na][1] + bv.y;
            float o2 = acc[ma][na][2] + bv.x;
            float o3 = acc[ma][na][3] + bv.y;
            if (act) { o0 = tanhf(o0); o1 = tanhf(o1); o2 = tanhf(o2); o3 = tanhf(o3); }
            if (rdst[ma][0] >= 0)
                *(float2*)&C[(size_t)rdst[ma][0] * N + col] = make_float2(o0, o1);
            if (rdst[ma][1] >= 0)
                *(float2*)&C[(size_t)rdst[ma][1] * N + col] = make_float2(o2, o3);
        }
    }
}

// ---------------- persistent bidirectional RNN: R14 shape + cluster barrier -----
// grid 128 = 8 clusters of 16. Cluster = (dir, bgroup of 8). CTA = jgroup of 32.
// barrier.cluster.arrive/wait replaces the software global barrier entirely
// (arrive=release covers h stores; wait=acquire covers peer h loads; the
// barrier is a full thread rendezvous so no __syncthreads needed around it).
#define RNN_SMEM ((8*512 + 32*516 + 8*264) * 4)

__global__ void __launch_bounds__(256, 1) rnn_kernel(
    const int* __restrict__ length,
    const float* __restrict__ Wf_h, const float* __restrict__ Wb_h)
{
    extern __shared__ float sm[];
    float4* h_s4 = (float4*)sm;               // [8][128] float4, col ^ b
    float*  Whs  = sm + 8 * 512;              // [32 j][516]
    float*  red  = Whs + 32 * 516;            // [warp][b*33 + j]

    const int tid  = threadIdx.x;
    const int wid  = tid >> 5;
    const int lane = tid & 31;
    const int bi   = lane >> 4;               // 0..1
    const int ji   = lane & 15;               // 0..15
    const int bx   = blockIdx.x;
    const int dir  = bx >> 6;
    const int bg   = (bx >> 4) & 3;
    const int jg   = bx & 15;
    const int b0   = bg * 8;
    const int j0   = jg * 32;
    const float* W = dir ? Wb_h : Wf_h;
    const float* U = dir ? g_Ub : g_Uf;
    float* hbase   = g_h + dir * 2 * (Bq*Hq);

    int smax = 1;
    #pragma unroll
    for (int i = 0; i < 8; ++i) { int Lg = length[b0 + i]; if (Lg > smax) smax = Lg; }

    // load W slice: Whs[j][k] = W[k][j0+j]
    for (int i = tid; i < 32 * 512; i += 256) {
        int j = i & 31, k = i >> 5;
        Whs[j * 516 + k] = W[k * Hq + j0 + j];
    }

    const int rb = tid >> 5;                  // 0..7 (local b for update phase)
    const int rj = tid & 31;                  // 0..31 (local j)
    const int L  = length[b0 + rb];
    float hprev = 0.f;

    const int kq0 = wid * 16;
    const int bA  = bi * 4;
    __syncthreads();

    for (int s = 0; s < smax; ++s) {
        const float4* hin4 = (const float4*)(hbase + (s & 1) * (Bq*Hq));
        float* hout        = hbase + ((s + 1) & 1) * (Bq*Hq);

        // ---- prefetch U (off critical path)
        float uval = 0.f;
        int tt = 0;
        if (s < L) {
            tt = dir ? (L - 1 - s) : s;
            uval = __ldcg(&U[((size_t)((b0 + rb) * Tq + tt)) * Hq + j0 + rj]);
        }

        // ---- stage this group's 8 h rows (16KB): 4 float4/thread
        #pragma unroll
        for (int it = 0; it < 4; ++it) {
            int f = tid + it * 256;
            int b = f >> 7, c4 = f & 127;
            h_s4[b * 128 + (c4 ^ b)] = __ldcg(hin4 + (b0 + b) * 128 + c4);
        }
        __syncthreads();

        // ---- compute partial dots (identical mix to R14)
        u64 acc[4][2];
        #pragma unroll
        for (int ib = 0; ib < 4; ++ib) { acc[ib][0] = 0ull; acc[ib][1] = 0ull; }

        #pragma unroll 8
        for (int it = 0; it < 16; ++it) {
            int kq = kq0 + it;
            int k  = kq * 4;
            float4 h0 = h_s4[(bA + 0) * 128 + (kq ^ (bA + 0))];
            float4 h1 = h_s4[(bA + 1) * 128 + (kq ^ (bA + 1))];
            float4 h2 = h_s4[(bA + 2) * 128 + (kq ^ (bA + 2))];
            float4 h3 = h_s4[(bA + 3) * 128 + (kq ^ (bA + 3))];
            ulonglong2 wA = *(const ulonglong2*)&Whs[ji * 516 + k];
            ulonglong2 wB = *(const ulonglong2*)&Whs[(ji + 16) * 516 + k];
            const ulonglong2* hv;
            hv = (const ulonglong2*)&h0;
            fma2(acc[0][0], hv->x, wA.x); fma2(acc[0][0], hv->y, wA.y);
            fma2(acc[0][1], hv->x, wB.x); fma2(acc[0][1], hv->y, wB.y);
            hv = (const ulonglong2*)&h1;
            fma2(acc[1][0], hv->x, wA.x); fma2(acc[1][0], hv->y, wA.y);
            fma2(acc[1][1], hv->x, wB.x); fma2(acc[1][1], hv->y, wB.y);
            hv = (const ulonglong2*)&h2;
            fma2(acc[2][0], hv->x, wA.x); fma2(acc[2][0], hv->y, wA.y);
            fma2(acc[2][1], hv->x, wB.x); fma2(acc[2][1], hv->y, wB.y);
            hv = (const ulonglong2*)&h3;
            fma2(acc[3][0], hv->x, wA.x); fma2(acc[3][0], hv->y, wA.y);
            fma2(acc[3][1], hv->x, wB.x); fma2(acc[3][1], hv->y, wB.y);
        }

        #pragma unroll
        for (int ib = 0; ib < 4; ++ib)
            #pragma unroll
            for (int ij = 0; ij < 2; ++ij) {
                float2 p = upk(acc[ib][ij]);
                red[wid * 264 + (bA + ib) * 33 + (ij ? ji + 16 : ji)] = p.x + p.y;
            }
        __syncthreads();

        float dot = 0.f;
        #pragma unroll
        for (int w = 0; w < 8; ++w) dot += red[w * 264 + rb * 33 + rj];

        float hnew;
        if (s < L) {
            hnew = tanhf(uval + dot);
            g_Z[((size_t)((b0 + rb) * Tq + tt)) * (2*Hq) + dir * Hq + j0 + rj] = hnew;
        } else {
            hnew = hprev;
        }
        hprev = hnew;
        hout[(b0 + rb) * Hq + j0 + rj] = hnew;

        // ---- hardware cluster barrier (release on arrive, acquire on wait)
        asm volatile("barrier.cluster.arrive.aligned;" ::: "memory");
        asm volatile("barrier.cluster.wait.aligned;" ::: "memory");
    }

    // final states straight from registers
    g_S[(size_t)(b0 + rb) * (2*Hq) + dir * Hq + j0 + rj] = hprev;
}

// ---------------- launcher ------------------------------------------------------
extern "C" void kernel_launch(void* const* d_in, const int* in_sizes, int n_in,
                              void* d_out, int out_size) {
    const float* x      = (const float*)d_in[0];
    const int*   length = (const int*)  d_in[1];
    const float* Wf     = (const float*)d_in[2];
    const float* bf     = (const float*)d_in[3];
    const float* Wb     = (const float*)d_in[4];
    const float* bb     = (const float*)d_in[5];
    const float* W1     = (const float*)d_in[6];
    const float* b1     = (const float*)d_in[7];
    const float* W2     = (const float*)d_in[8];
    const float* b2     = (const float*)d_in[9];
    float* out = (float*)d_out;

    void *pUf, *pUb, *pZ, *pA, *pS, *pAs, *pIdx, *pNv;
    cudaGetSymbolAddress(&pUf, g_Uf);
    cudaGetSymbolAddress(&pUb, g_Ub);
    cudaGetSymbolAddress(&pZ,  g_Z);
    cudaGetSymbolAddress(&pA,  g_A);
    cudaGetSymbolAddress(&pS,  g_S);
    cudaGetSymbolAddress(&pAs, g_As);
    cudaGetSymbolAddress(&pIdx, g_idx);
    cudaGetSymbolAddress(&pNv,  g_nv);
    const int* idx = (const int*)pIdx;
    const int* nv  = (const int*)pNv;

    cudaFuncSetAttribute(rnn_kernel, cudaFuncAttributeMaxDynamicSharedMemorySize, RNN_SMEM);
    cudaFuncSetAttribute(rnn_kernel, cudaFuncAttributeNonPortableClusterSizeAllowed, 1);

    const int M = Bq * Tq;   // 16384

    init_kernel<<<64, 256>>>();
    scan_kernel<<<1, 32>>>(length);
    idx_kernel<<<(M + 255)/256, 256>>>(length);
    c2_part_kernel<<<dim3(4, 16), 256>>>(b1, W2);
    c2_sum_kernel<<<(2*Hq + 255)/256, 256>>>(b2);
    fill_kernel<<<M, 64>>>(length, out);

    gemm_tc<<<dim3(Hq/128, M/128), 256>>>(x, Wf, bf, (float*)pUf, M, Hq, Hq, 0, idx, idx, nv);
    gemm_tc<<<dim3(Hq/128, M/128), 256>>>(x, Wb, bb, (float*)pUb, M, Hq, Hq, 0, idx, idx, nv);

    // rnn: 8 clusters of 16 CTAs (cluster = one barrier group)
    {
        cudaLaunchConfig_t cfg = {};
        cfg.gridDim  = dim3(128, 1, 1);
        cfg.blockDim = dim3(256, 1, 1);
        cfg.dynamicSmemBytes = RNN_SMEM;
        cfg.stream = 0;
        cudaLaunchAttribute attrs[1];
        attrs[0].id = cudaLaunchAttributeClusterDimension;
        attrs[0].val.clusterDim.x = 16;
        attrs[0].val.clusterDim.y = 1;
        attrs[0].val.clusterDim.z = 1;
        cfg.attrs = attrs;
        cfg.numAttrs = 1;
        cudaLaunchKernelEx(&cfg, rnn_kernel, length, Wf + Hq*Hq, Wb + Hq*Hq);
    }

    gemm_tc<<<dim3(FFq/128, M/128), 256>>>((const float*)pZ, W1, b1, (float*)pA, M, FFq, 2*Hq, 1, idx, (const int*)0, nv);
    gemm_tc<<<dim3((2*Hq)/128, M/128), 256>>>((const float*)pA, W2, b2, out, M, 2*Hq, FFq, 0, (const int*)0, idx, nv);

    gemm_tc<<<dim3(FFq/128, 1), 256>>>((const float*)pS, W1, b1, (float*)pAs, Bq, FFq, 2*Hq, 1, (const int*)0, (const int*)0, (const int*)0);
    gemm_tc<<<dim3((2*Hq)/128, 1), 256>>>((const float*)pAs, W2, b2, out + (size_t)M * 2 * Hq, Bq, 2*Hq, FFq, 0, (const int*)0, (const int*)0, (const int*)0);
}

// round 17
// speedup vs baseline: 1.0438x; 1.0168x over previous
#include <cuda_runtime.h>

#define Bq 32
#define Tq 512
#define Hq 512
#define FFq 2048

typedef unsigned long long u64;
typedef unsigned int u32;

// ---------------- static device scratch ---------------------------------------
__device__ float g_Uf[Bq*Tq*Hq];
__device__ float g_Ub[Bq*Tq*Hq];
__device__ float g_Z [Bq*Tq*2*Hq];
__device__ float g_A [Bq*Tq*FFq];
__device__ float g_h [2*2*Bq*Hq];       // [dir][pingpong][b*H+j]
__device__ float g_S [Bq*2*Hq];
__device__ float g_As[Bq*FFq];
__device__ int   g_off[Bq];
__device__ int   g_nv;
__device__ int   g_idx[Bq*Tq];
__device__ float g_tb1[FFq];
__device__ float g_c2p[16][2*Hq];
__device__ float g_c2[2*Hq];

__device__ __forceinline__ u64 pk2(float lo, float hi) {
    u64 r; asm("mov.b64 %0, {%1, %2};" : "=l"(r) : "f"(lo), "f"(hi)); return r;
}
__device__ __forceinline__ void fma2(u64& d, u64 a, u64 b) {
    asm("fma.rn.f32x2 %0, %1, %2, %0;" : "+l"(d) : "l"(a), "l"(b));
}
__device__ __forceinline__ float2 upk(u64 v) {
    float2 f; asm("mov.b64 {%0, %1}, %2;" : "=f"(f.x), "=f"(f.y) : "l"(v)); return f;
}
__device__ __forceinline__ u32 f2tf32(float f) {
    u32 r; asm("cvt.rna.tf32.f32 %0, %1;" : "=r"(r) : "f"(f)); return r;
}

// ---------------- init ----------------------------------------------------------
__global__ void init_kernel() {
    int idx = blockIdx.x * blockDim.x + threadIdx.x;
    if (idx < (2*2*Bq*Hq)/4)
        ((float4*)g_h)[idx] = make_float4(0.f, 0.f, 0.f, 0.f);
}

// ---------------- compaction helpers -------------------------------------------
__global__ void scan_kernel(const int* __restrict__ length) {
    if (threadIdx.x == 0 && blockIdx.x == 0) {
        int acc = 0;
        for (int b = 0; b < Bq; ++b) { g_off[b] = acc; acc += length[b]; }
        g_nv = acc;
    }
}

__global__ void idx_kernel(const int* __restrict__ length) {
    int i = blockIdx.x * blockDim.x + threadIdx.x;
    if (i < Bq * Tq) {
        int b = i >> 9, t = i & 511;
        if (t < length[b]) g_idx[g_off[b] + t] = i;
    }
}

__global__ void tanhb1_kernel(const float* __restrict__ b1) {
    int f = blockIdx.x * blockDim.x + threadIdx.x;
    if (f < FFq) g_tb1[f] = tanhf(b1[f]);
}

__global__ void c2_part_kernel(const float* __restrict__ W2) {
    int n = blockIdx.x * blockDim.x + threadIdx.x;
    int f0 = blockIdx.y * 128;
    float s = 0.f;
    for (int f = f0; f < f0 + 128; ++f)
        s += g_tb1[f] * W2[(size_t)f * 2*Hq + n];
    g_c2p[blockIdx.y][n] = s;
}

__global__ void c2_sum_kernel(const float* __restrict__ b2) {
    int n = blockIdx.x * blockDim.x + threadIdx.x;
    if (n < 2*Hq) {
        float s = 0.f;
        #pragma unroll
        for (int p = 0; p < 16; ++p) s += g_c2p[p][n];
        g_c2[n] = s + b2[n];
    }
}

// fill invalid out rows with c2; each block handles 8 m-rows with 256 threads
__global__ void fill_kernel(const int* __restrict__ length, float* __restrict__ out) {
    int m0 = blockIdx.x * 8;
    const float4* c = (const float4*)g_c2;
    int r = threadIdx.x >> 5;           // 0..7 local row
    int lane = threadIdx.x & 31;
    int m = m0 + r;
    int b = m >> 9, t = m & 511;
    if (t >= length[b]) {
        float4* o = (float4*)(out + (size_t)m * 2*Hq);
        #pragma unroll
        for (int i = 0; i < 8; ++i) o[lane + i*32] = c[lane + i*32];
    }
}

// ---------------- TF32 tensor-core GEMM (unchanged) -----------------------------
#define MMA_TF32(d, a, b0, b1)                                                  \
    asm volatile("mma.sync.aligned.m16n8k8.row.col.f32.tf32.tf32.f32 "          \
        "{%0,%1,%2,%3}, {%4,%5,%6,%7}, {%8,%9}, {%0,%1,%2,%3};"                 \
        : "+f"(d[0]), "+f"(d[1]), "+f"(d[2]), "+f"(d[3])                        \
        : "r"(a[0]), "r"(a[1]), "r"(a[2]), "r"(a[3]), "r"(b0), "r"(b1))

__global__ void __launch_bounds__(256, 2) gemm_tc(
    const float* __restrict__ A, const float* __restrict__ B,
    const float* __restrict__ bias, float* __restrict__ C,
    int M, int N, int K, int act,
    const int* __restrict__ idxA, const int* __restrict__ idxC,
    const int* __restrict__ nvp)
{
    __shared__ u32 As_t[32*132];
    __shared__ u32 Bs  [32*132];

    const int bn = blockIdx.x, bm = blockIdx.y;
    const int Meff = nvp ? *nvp : M;
    if (bm * 128 >= Meff) return;

    const int tid  = threadIdx.x;
    const int wid  = tid >> 5;
    const int lane = tid & 31;
    const int g    = lane >> 2;
    const int t4   = lane & 3;
    const int warpM = (wid & 3) * 32;
    const int warpN = (wid >> 2) * 64;

    float acc[2][8][4];
    #pragma unroll
    for (int ma = 0; ma < 2; ++ma)
        #pragma unroll
        for (int na = 0; na < 8; ++na)
            #pragma unroll
            for (int c = 0; c < 4; ++c) acc[ma][na][c] = 0.f;

    const int arow = tid >> 1;
    const int akb  = (tid & 1) * 16;
    const int brow = tid >> 3;
    const int bcg  = (tid & 7) * 16;
    const int grow = bm * 128 + arow;
    const bool aok = grow < Meff;
    const int ra = aok ? (idxA ? idxA[grow] : grow) : 0;
    const float* Ap = A + (size_t)ra * K + akb;
    const float* Bp = B + (size_t)brow * N + bn * 128 + bcg;

    float4 pa[4], pb[4];
    #pragma unroll
    for (int q = 0; q < 4; ++q) {
        pa[q] = aok ? *(const float4*)(Ap + 4*q) : make_float4(0.f,0.f,0.f,0.f);
        pb[q] = *(const float4*)(Bp + 4*q);
    }

    for (int k0 = 0; k0 < K; k0 += 32) {
        __syncthreads();
        #pragma unroll
        for (int q = 0; q < 4; ++q) {
            const float* e = (const float*)&pa[q];
            #pragma unroll
            for (int c = 0; c < 4; ++c)
                As_t[(akb + 4*q + c)*132 + arow] = f2tf32(e[c]);
            const float* f = (const float*)&pb[q];
            #pragma unroll
            for (int c = 0; c < 4; ++c)
                Bs[brow*132 + bcg + 4*q + c] = f2tf32(f[c]);
        }
        __syncthreads();

        if (k0 + 32 < K) {
            #pragma unroll
            for (int q = 0; q < 4; ++q) {
                pa[q] = aok ? *(const float4*)(Ap + k0 + 32 + 4*q)
                            : make_float4(0.f,0.f,0.f,0.f);
                pb[q] = *(const float4*)(Bp + (size_t)(k0 + 32) * N + 4*q);
            }
        }

        #pragma unroll
        for (int kk = 0; kk < 4; ++kk) {
            const int kof = kk * 8;
            u32 afr[2][4];
            const int ab = (kof + t4)*132 + warpM + g;
            #pragma unroll
            for (int ma = 0; ma < 2; ++ma) {
                afr[ma][0] = As_t[ab + ma*16];
                afr[ma][1] = As_t[ab + ma*16 + 8];
                afr[ma][2] = As_t[ab + ma*16 + 4*132];
                afr[ma][3] = As_t[ab + ma*16 + 8 + 4*132];
            }
            const int bb = (kof + t4)*132 + warpN + g;
            #pragma unroll
            for (int na = 0; na < 8; ++na) {
                u32 b0 = Bs[bb + na*8];
                u32 b1 = Bs[bb + na*8 + 4*132];
                MMA_TF32(acc[0][na], afr[0], b0, b1);
                MMA_TF32(acc[1][na], afr[1], b0, b1);
            }
        }
    }

    int rdst[2][2];
    #pragma unroll
    for (int ma = 0; ma < 2; ++ma)
        #pragma unroll
        for (int h = 0; h < 2; ++h) {
            int r = bm * 128 + warpM + ma*16 + g + h*8;
            rdst[ma][h] = (r < Meff) ? (idxC ? idxC[r] : r) : -1;
        }

    #pragma unroll
    for (int na = 0; na < 8; ++na) {
        const int col = bn * 128 + warpN + na*8 + 2*t4;
        const float2 bv = *(const float2*)&bias[col];
        #pragma unroll
        for (int ma = 0; ma < 2; ++ma) {
            float o0 = acc[ma][na][0] + bv.x;
            float o1 = acc[ma][na][1] + bv.y;
            float o2 = acc[ma][na][2] + bv.x;
            float o3 = acc[ma][na][3] + bv.y;
            if (act) { o0 = tanhf(o0); o1 = tanhf(o1); o2 = tanhf(o2); o3 = tanhf(o3); }
            if (rdst[ma][0] >= 0)
                *(float2*)&C[(size_t)rdst[ma][0] * N + col] = make_float2(o0, o1);
            if (rdst[ma][1] >= 0)
                *(float2*)&C[(size_t)rdst[ma][1] * N + col] = make_float2(o2, o3);
        }
    }
}

// ---------------- persistent bidirectional RNN: cluster barrier + per-warp stage -
// grid 128 = 8 clusters of 16. Cluster = (dir, bgroup of 8). CTA = jgroup of 32.
// Staging is PER-WARP: warp w loads rows 0..7 of its own 64-k slice (2KB) into
// a private smem region — no cross-warp staging sync (just __syncwarp).
#define RNN_SMEM ((8*128*4 + 32*516 + 8*264) * 4)

__global__ void __launch_bounds__(256, 1) rnn_kernel(
    const int* __restrict__ length,
    const float* __restrict__ Wf_h, const float* __restrict__ Wb_h)
{
    extern __shared__ float sm[];
    float4* hW   = (float4*)sm;               // [warp][8 rows][16 f4] (2KB/warp)
    float*  Whs  = sm + 8 * 128 * 4;          // [32 j][516]
    float*  red  = Whs + 32 * 516;            // [warp][b*33 + j]

    const int tid  = threadIdx.x;
    const int wid  = tid >> 5;
    const int lane = tid & 31;
    const int bi   = lane >> 4;               // 0..1
    const int ji   = lane & 15;               // 0..15
    const int bx   = blockIdx.x;
    const int dir  = bx >> 6;
    const int bg   = (bx >> 4) & 3;
    const int jg   = bx & 15;
    const int b0   = bg * 8;
    const int j0   = jg * 32;
    const float* W = dir ? Wb_h : Wf_h;
    const float* U = dir ? g_Ub : g_Uf;
    float* hbase   = g_h + dir * 2 * (Bq*Hq);

    int smax = 1;
    #pragma unroll
    for (int i = 0; i < 8; ++i) { int Lg = length[b0 + i]; if (Lg > smax) smax = Lg; }

    // load W slice: Whs[j][k] = W[k][j0+j]
    for (int i = tid; i < 32 * 512; i += 256) {
        int j = i & 31, k = i >> 5;
        Whs[j * 516 + k] = W[k * Hq + j0 + j];
    }

    const int rb = tid >> 5;                  // 0..7 (local b for update phase)
    const int rj = tid & 31;                  // 0..31 (local j)
    const int L  = length[b0 + rb];
    float hprev = 0.f;

    const int kq0 = wid * 16;                 // float4 k-offset of warp's slice
    const int bA  = bi * 4;
    float4* hMe = hW + wid * 128;             // this warp's private region
    // staging identity: lane covers f = lane + i*32; row = f>>4, c16 = f&15
    __syncthreads();

    for (int s = 0; s < smax; ++s) {
        const float4* hin4 = (const float4*)(hbase + (s & 1) * (Bq*Hq));
        float* hout        = hbase + ((s + 1) & 1) * (Bq*Hq);

        // ---- prefetch U (off critical path)
        float uval = 0.f;
        int tt = 0;
        if (s < L) {
            tt = dir ? (L - 1 - s) : s;
            uval = __ldcg(&U[((size_t)((b0 + rb) * Tq + tt)) * Hq + j0 + rj]);
        }

        // ---- per-warp stage: 8 rows x 16 float4 of this warp's k-slice
        #pragma unroll
        for (int i = 0; i < 4; ++i) {
            int f = lane + i * 32;
            int row = f >> 4, c16 = f & 15;
            hMe[row * 16 + c16] = __ldcg(hin4 + (b0 + row) * 128 + kq0 + c16);
        }
        __syncwarp();

        // ---- compute partial dots (same arithmetic as R14/R16)
        u64 acc[4][2];
        #pragma unroll
        for (int ib = 0; ib < 4; ++ib) { acc[ib][0] = 0ull; acc[ib][1] = 0ull; }

        #pragma unroll 8
        for (int it = 0; it < 16; ++it) {
            int k = (kq0 + it) * 4;
            float4 h0 = hMe[(bA + 0) * 16 + it];
            float4 h1 = hMe[(bA + 1) * 16 + it];
            float4 h2 = hMe[(bA + 2) * 16 + it];
            float4 h3 = hMe[(bA + 3) * 16 + it];
            ulonglong2 wA = *(const ulonglong2*)&Whs[ji * 516 + k];
            ulonglong2 wB = *(const ulonglong2*)&Whs[(ji + 16) * 516 + k];
            const ulonglong2* hv;
            hv = (const ulonglong2*)&h0;
            fma2(acc[0][0], hv->x, wA.x); fma2(acc[0][0], hv->y, wA.y);
            fma2(acc[0][1], hv->x, wB.x); fma2(acc[0][1], hv->y, wB.y);
            hv = (const ulonglong2*)&h1;
            fma2(acc[1][0], hv->x, wA.x); fma2(acc[1][0], hv->y, wA.y);
            fma2(acc[1][1], hv->x, wB.x); fma2(acc[1][1], hv->y, wB.y);
            hv = (const ulonglong2*)&h2;
            fma2(acc[2][0], hv->x, wA.x); fma2(acc[2][0], hv->y, wA.y);
            fma2(acc[2][1], hv->x, wB.x); fma2(acc[2][1], hv->y, wB.y);
            hv = (const ulonglong2*)&h3;
            fma2(acc[3][0], hv->x, wA.x); fma2(acc[3][0], hv->y, wA.y);
            fma2(acc[3][1], hv->x, wB.x); fma2(acc[3][1], hv->y, wB.y);
        }

        #pragma unroll
        for (int ib = 0; ib < 4; ++ib)
            #pragma unroll
            for (int ij = 0; ij < 2; ++ij) {
                float2 p = upk(acc[ib][ij]);
                red[wid * 264 + (bA + ib) * 33 + (ij ? ji + 16 : ji)] = p.x + p.y;
            }
        __syncthreads();

        float dot = 0.f;
        #pragma unroll
        for (int w = 0; w < 8; ++w) dot += red[w * 264 + rb * 33 + rj];

        float hnew;
        if (s < L) {
            hnew = tanhf(uval + dot);
            g_Z[((size_t)((b0 + rb) * Tq + tt)) * (2*Hq) + dir * Hq + j0 + rj] = hnew;
        } else {
            hnew = hprev;
        }
        hprev = hnew;
        hout[(b0 + rb) * Hq + j0 + rj] = hnew;

        // ---- hardware cluster barrier (release on arrive, acquire on wait)
        asm volatile("barrier.cluster.arrive.aligned;" ::: "memory");
        asm volatile("barrier.cluster.wait.aligned;" ::: "memory");
    }

    // final states straight from registers
    g_S[(size_t)(b0 + rb) * (2*Hq) + dir * Hq + j0 + rj] = hprev;
}

// ---------------- launcher ------------------------------------------------------
extern "C" void kernel_launch(void* const* d_in, const int* in_sizes, int n_in,
                              void* d_out, int out_size) {
    const float* x      = (const float*)d_in[0];
    const int*   length = (const int*)  d_in[1];
    const float* Wf     = (const float*)d_in[2];
    const float* bf     = (const float*)d_in[3];
    const float* Wb     = (const float*)d_in[4];
    const float* bb     = (const float*)d_in[5];
    const float* W1     = (const float*)d_in[6];
    const float* b1     = (const float*)d_in[7];
    const float* W2     = (const float*)d_in[8];
    const float* b2     = (const float*)d_in[9];
    float* out = (float*)d_out;

    void *pUf, *pUb, *pZ, *pA, *pS, *pAs, *pIdx, *pNv;
    cudaGetSymbolAddress(&pUf, g_Uf);
    cudaGetSymbolAddress(&pUb, g_Ub);
    cudaGetSymbolAddress(&pZ,  g_Z);
    cudaGetSymbolAddress(&pA,  g_A);
    cudaGetSymbolAddress(&pS,  g_S);
    cudaGetSymbolAddress(&pAs, g_As);
    cudaGetSymbolAddress(&pIdx, g_idx);
    cudaGetSymbolAddress(&pNv,  g_nv);
    const int* idx = (const int*)pIdx;
    const int* nv  = (const int*)pNv;

    cudaFuncSetAttribute(rnn_kernel, cudaFuncAttributeMaxDynamicSharedMemorySize, RNN_SMEM);
    cudaFuncSetAttribute(rnn_kernel, cudaFuncAttributeNonPortableClusterSizeAllowed, 1);

    const int M = Bq * Tq;   // 16384

    init_kernel<<<64, 256>>>();
    scan_kernel<<<1, 32>>>(length);
    idx_kernel<<<(M + 255)/256, 256>>>(length);
    tanhb1_kernel<<<(FFq + 255)/256, 256>>>(b1);
    c2_part_kernel<<<dim3(4, 16), 256>>>(W2);
    c2_sum_kernel<<<(2*Hq + 255)/256, 256>>>(b2);
    fill_kernel<<<M/8, 256>>>(length, out);

    gemm_tc<<<dim3(Hq/128, M/128), 256>>>(x, Wf, bf, (float*)pUf, M, Hq, Hq, 0, idx, idx, nv);
    gemm_tc<<<dim3(Hq/128, M/128), 256>>>(x, Wb, bb, (float*)pUb, M, Hq, Hq, 0, idx, idx, nv);

    // rnn: 8 clusters of 16 CTAs (cluster = one barrier group)
    {
        cudaLaunchConfig_t cfg = {};
        cfg.gridDim  = dim3(128, 1, 1);
        cfg.blockDim = dim3(256, 1, 1);
        cfg.dynamicSmemBytes = RNN_SMEM;
        cfg.stream = 0;
        cudaLaunchAttribute attrs[1];
        attrs[0].id = cudaLaunchAttributeClusterDimension;
        attrs[0].val.clusterDim.x = 16;
        attrs[0].val.clusterDim.y = 1;
        attrs[0].val.clusterDim.z = 1;
        cfg.attrs = attrs;
        cfg.numAttrs = 1;
        cudaLaunchKernelEx(&cfg, rnn_kernel, length, Wf + Hq*Hq, Wb + Hq*Hq);
    }

    gemm_tc<<<dim3(FFq/128, M/128), 256>>>((const float*)pZ, W1, b1, (float*)pA, M, FFq, 2*Hq, 1, idx, (const int*)0, nv);
    gemm_tc<<<dim3((2*Hq)/128, M/128), 256>>>((const float*)pA, W2, b2, out, M, 2*Hq, FFq, 0, (const int*)0, idx, nv);

    gemm_tc<<<dim3(FFq/128, 1), 256>>>((const float*)pS, W1, b1, (float*)pAs, Bq, FFq, 2*Hq, 1, (const int*)0, (const int*)0, (const int*)0);
    gemm_tc<<<dim3((2*Hq)/128, 1), 256>>>((const float*)pAs, W2, b2, out + (size_t)M * 2 * Hq, Bq, 2*Hq, FFq, 0, (const int*)0, (const int*)0, (const int*)0);
}